// round 5
// baseline (speedup 1.0000x reference)
#include <cuda_runtime.h>
#include <cstdint>

// Problem constants
#define N_VIS     64
#define ALPHA     4
#define GIBBS_K   10
#define BATCH     65536
#define PAIRS     32768          // BATCH/2 : warp handles (b, b+PAIRS)
#define WPB       8              // warps per block
#define TPB       (WPB*32)
#define NBLOCKS   (PAIRS/WPB)    // 4096

#define HALF_H 8388608u          // (BATCH*ALPHA*N_VIS)/2
#define HALF_V 2097152u          // (BATCH*N_VIS)/2

struct RbmKeys { uint2 kh[GIBBS_K]; uint2 kv[GIBBS_K]; };

__device__ double g_rbm_partials[NBLOCKS];

// ---------------------------------------------------------------------------
// JAX threefry2x32 (exact replication of jax._src.prng implementation)
// ---------------------------------------------------------------------------
__host__ __device__ __forceinline__ unsigned rbm_rotl32(unsigned x, int r) {
    return (x << r) | (x >> (32 - r));
}

__host__ __device__ __forceinline__ void rbm_tf2x32(unsigned k0, unsigned k1,
                                                    unsigned x0, unsigned x1,
                                                    unsigned& o0, unsigned& o1) {
    unsigned ks2 = k0 ^ k1 ^ 0x1BD11BDAu;
    x0 += k0; x1 += k1;
#define TFR(r) { x0 += x1; x1 = rbm_rotl32(x1, r); x1 ^= x0; }
    TFR(13) TFR(15) TFR(26) TFR(6)
    x0 += k1;  x1 += ks2 + 1u;
    TFR(17) TFR(29) TFR(16) TFR(24)
    x0 += ks2; x1 += k0 + 2u;
    TFR(13) TFR(15) TFR(26) TFR(6)
    x0 += k0;  x1 += k1 + 3u;
    TFR(17) TFR(29) TFR(16) TFR(24)
    x0 += k1;  x1 += ks2 + 4u;
    TFR(13) TFR(15) TFR(26) TFR(6)
    x0 += ks2; x1 += k0 + 5u;
#undef TFR
    o0 = x0; o1 = x1;
}

// jax.random.uniform float32 bit convention: bitcast(bits>>9 | 0x3f800000) - 1
__device__ __forceinline__ float rbm_u01(unsigned b) {
    return __uint_as_float((b >> 9) | 0x3f800000u) - 1.0f;
}

// XLA logistic expander: sigmoid(x) = 0.5 + 0.5*tanh(0.5*x)
__device__ __forceinline__ float rbm_sigmoid(float x) {
    return 0.5f + 0.5f * tanhf(0.5f * x);
}

// jnp.logaddexp(x, 0) = max(x,0) + log1p(exp(-|x|))
__device__ __forceinline__ float rbm_softplus(float x) {
    return fmaxf(x, 0.0f) + log1pf(expf(-fabsf(x)));
}

__device__ __forceinline__ unsigned long long rbm_rotr64(unsigned long long x, int s) {
    s &= 63;
    if (s == 0) return x;
    return (x >> s) | (x << (64 - s));
}

__device__ __forceinline__ float rbm_warp_sum(float v) {
    #pragma unroll
    for (int s = 16; s > 0; s >>= 1) v += __shfl_xor_sync(0xffffffffu, v, s);
    return v;
}

// ---------------------------------------------------------------------------
// wv[a][i] = sum_m kernel[a][(m-i)%64] * v[m]
//          = sum_c Tf[a][nib_c(v)][(4c - i) & 63]
// Tf[a][n][o] = sum_{t<4} K[a][(o+t)&63] * bit_t(n)   (16 KB shared)
// acc layout: acc[a*2 + ii], ii=0 -> i=lane, ii=1 -> i=lane+32
// ---------------------------------------------------------------------------
__device__ __forceinline__ void rbm_compute_wv(unsigned long long m, int lane,
                                               const float* __restrict__ Tf,
                                               float acc[8]) {
    #pragma unroll
    for (int k = 0; k < 8; k++) acc[k] = 0.0f;
    int off = (-lane) & 63;
    unsigned long long vv = m;
    #pragma unroll
    for (int c = 0; c < 16; c++) {
        int n = (int)((unsigned)vv & 15u);
        vv >>= 4;
        const float* T = Tf + n * 64;
        int o1 = off ^ 32;
        #pragma unroll
        for (int a = 0; a < 4; a++) {
            acc[a * 2 + 0] += T[a * 1024 + off];
            acc[a * 2 + 1] += T[a * 1024 + o1];
        }
        off = (off + 4) & 63;
    }
}

// ---------------------------------------------------------------------------
// wh[i] = sum_a sum_j K[a][j] * h_a[(i-1-j)&63]
//       = sum_a sum_c Tn[a][c][nib], nib = bits h_a[(i-1-4c-t)], t=0..3
// With hr = brev64(h_a), rr = rotr64(hr, (64-i)&63): nib_c = (rr >> 4c) & 15
// Tn[a][c][n] = sum_{t<4} K[a][4c+t] * bit_t(n)       (1 KB shared)
// ---------------------------------------------------------------------------
__device__ __forceinline__ void rbm_compute_wh(const unsigned long long h[4], int lane,
                                               const float* __restrict__ Tn,
                                               float& wh0, float& wh1) {
    unsigned long long r0[4], r1[4];
    #pragma unroll
    for (int a = 0; a < 4; a++) {
        unsigned long long hr = __brevll(h[a]);
        r0[a] = rbm_rotr64(hr, (64 - lane) & 63);
        r1[a] = rbm_rotr64(hr, (32 - lane) & 63);
    }
    wh0 = 0.0f; wh1 = 0.0f;
    #pragma unroll
    for (int c = 0; c < 16; c++) {
        #pragma unroll
        for (int a = 0; a < 4; a++) {
            wh0 += Tn[a * 256 + c * 16 + (int)((unsigned)r0[a] & 15u)];
            wh1 += Tn[a * 256 + c * 16 + (int)((unsigned)r1[a] & 15u)];
            r0[a] >>= 4;
            r1[a] >>= 4;
        }
    }
}

__device__ __forceinline__ float rbm_free_energy(unsigned long long m, int lane,
                                                 const float* __restrict__ Tf,
                                                 const float* __restrict__ csh,
                                                 float bsc) {
    float acc[8];
    rbm_compute_wv(m, lane, Tf, acc);
    float s = 0.0f;
    #pragma unroll
    for (int a = 0; a < 4; a++) {
        float ca = csh[a];
        s += rbm_softplus(acc[a * 2 + 0] + ca);
        s += rbm_softplus(acc[a * 2 + 1] + ca);
    }
    s = rbm_warp_sum(s);
    return -bsc * (float)__popcll(m) - s;
}

// ---------------------------------------------------------------------------
// Main kernel: one warp per sample pair (b, b+32768)
// ---------------------------------------------------------------------------
__global__ void __launch_bounds__(TPB)
rbm_gibbs_kernel(const float* __restrict__ v_data,
                 const float* __restrict__ kern,    // [ALPHA][64]
                 const float* __restrict__ b_scalar,
                 const float* __restrict__ c_vector,
                 RbmKeys keys) {
    __shared__ float Tf[4 * 16 * 64];   // 16 KB
    __shared__ float Tn[4 * 16 * 16];   // 1 KB
    __shared__ float csh[4];
    __shared__ double wsum[WPB];

    const int tid  = threadIdx.x;
    const int lane = tid & 31;
    const int wid  = tid >> 5;

    // Build Tf
    for (int idx = tid; idx < 4 * 16 * 64; idx += TPB) {
        int o = idx & 63, n = (idx >> 6) & 15, a = idx >> 10;
        float s = 0.0f;
        #pragma unroll
        for (int t = 0; t < 4; t++)
            if ((n >> t) & 1) s += kern[a * 64 + ((o + t) & 63)];
        Tf[a * 1024 + n * 64 + o] = s;
    }
    // Build Tn
    for (int idx = tid; idx < 4 * 16 * 16; idx += TPB) {
        int n = idx & 15, c = (idx >> 4) & 15, a = idx >> 8;
        float s = 0.0f;
        #pragma unroll
        for (int t = 0; t < 4; t++)
            if ((n >> t) & 1) s += kern[a * 64 + c * 4 + t];
        Tn[a * 256 + c * 16 + n] = s;
    }
    if (tid < 4) csh[tid] = c_vector[tid];
    __syncthreads();

    const float bsc = b_scalar[0];
    const int w  = blockIdx.x * WPB + wid;   // pair index in [0, PAIRS)
    const int b0 = w;
    const int b1 = w + PAIRS;

    // Load v_data as bitmasks (bit i = v[i] != 0)
    unsigned long long m0, m1;
    {
        float a0 = v_data[(size_t)b0 * 64 + lane];
        float a1 = v_data[(size_t)b0 * 64 + lane + 32];
        unsigned lo = __ballot_sync(0xffffffffu, a0 != 0.0f);
        unsigned hi = __ballot_sync(0xffffffffu, a1 != 0.0f);
        m0 = (unsigned long long)lo | ((unsigned long long)hi << 32);
        float b0f = v_data[(size_t)b1 * 64 + lane];
        float b1f = v_data[(size_t)b1 * 64 + lane + 32];
        lo = __ballot_sync(0xffffffffu, b0f != 0.0f);
        hi = __ballot_sync(0xffffffffu, b1f != 0.0f);
        m1 = (unsigned long long)lo | ((unsigned long long)hi << 32);
    }

    const float fed0 = rbm_free_energy(m0, lane, Tf, csh, bsc);
    const float fed1 = rbm_free_energy(m1, lane, Tf, csh, bsc);

    // Gibbs chain
    #pragma unroll 1
    for (int t = 0; t < GIBBS_K; t++) {
        float acc0[8], acc1[8];
        rbm_compute_wv(m0, lane, Tf, acc0);
        rbm_compute_wv(m1, lane, Tf, acc1);

        const uint2 kh = keys.kh[t];
        const unsigned baseH = (unsigned)b0 * 256u;
        unsigned long long h0[4], h1[4];
        #pragma unroll
        for (int a = 0; a < 4; a++) {
            const float ca = csh[a];
            unsigned cA = baseH + (unsigned)(a * 64 + lane);       // ii=0
            unsigned cB = cA + 32u;                                 // ii=1
            unsigned rA0, rA1, rB0, rB1;
            rbm_tf2x32(kh.x, kh.y, cA, cA + HALF_H, rA0, rA1);
            rbm_tf2x32(kh.x, kh.y, cB, cB + HALF_H, rB0, rB1);
            bool s0i0 = rbm_u01(rA0) < rbm_sigmoid(acc0[a * 2 + 0] + ca);
            bool s1i0 = rbm_u01(rA1) < rbm_sigmoid(acc1[a * 2 + 0] + ca);
            bool s0i1 = rbm_u01(rB0) < rbm_sigmoid(acc0[a * 2 + 1] + ca);
            bool s1i1 = rbm_u01(rB1) < rbm_sigmoid(acc1[a * 2 + 1] + ca);
            unsigned lo0 = __ballot_sync(0xffffffffu, s0i0);
            unsigned hi0 = __ballot_sync(0xffffffffu, s0i1);
            unsigned lo1 = __ballot_sync(0xffffffffu, s1i0);
            unsigned hi1 = __ballot_sync(0xffffffffu, s1i1);
            h0[a] = (unsigned long long)lo0 | ((unsigned long long)hi0 << 32);
            h1[a] = (unsigned long long)lo1 | ((unsigned long long)hi1 << 32);
        }

        float wh00, wh01, wh10, wh11;
        rbm_compute_wh(h0, lane, Tn, wh00, wh01);
        rbm_compute_wh(h1, lane, Tn, wh10, wh11);

        const uint2 kv = keys.kv[t];
        const unsigned baseV = (unsigned)b0 * 64u + (unsigned)lane;
        unsigned r00, r01, r10, r11;
        rbm_tf2x32(kv.x, kv.y, baseV,       baseV + HALF_V,       r00, r01);
        rbm_tf2x32(kv.x, kv.y, baseV + 32u, baseV + 32u + HALF_V, r10, r11);
        bool s0i0 = rbm_u01(r00) < rbm_sigmoid(wh00 + bsc);
        bool s1i0 = rbm_u01(r01) < rbm_sigmoid(wh10 + bsc);
        bool s0i1 = rbm_u01(r10) < rbm_sigmoid(wh01 + bsc);
        bool s1i1 = rbm_u01(r11) < rbm_sigmoid(wh11 + bsc);
        unsigned lo0 = __ballot_sync(0xffffffffu, s0i0);
        unsigned hi0 = __ballot_sync(0xffffffffu, s0i1);
        unsigned lo1 = __ballot_sync(0xffffffffu, s1i0);
        unsigned hi1 = __ballot_sync(0xffffffffu, s1i1);
        m0 = (unsigned long long)lo0 | ((unsigned long long)hi0 << 32);
        m1 = (unsigned long long)lo1 | ((unsigned long long)hi1 << 32);
    }

    const float fem0 = rbm_free_energy(m0, lane, Tf, csh, bsc);
    const float fem1 = rbm_free_energy(m1, lane, Tf, csh, bsc);
    const float diff = (fed0 - fem0) + (fed1 - fem1);

    if (lane == 0) wsum[wid] = (double)diff;
    __syncthreads();
    if (tid == 0) {
        double s = 0.0;
        #pragma unroll
        for (int i = 0; i < WPB; i++) s += wsum[i];
        g_rbm_partials[blockIdx.x] = s;
    }
}

__global__ void __launch_bounds__(256)
rbm_reduce_kernel(float* __restrict__ out) {
    __shared__ double sh[256];
    const int t = threadIdx.x;
    double s = 0.0;
    for (int i = t; i < NBLOCKS; i += 256) s += g_rbm_partials[i];
    sh[t] = s;
    __syncthreads();
    #pragma unroll
    for (int str = 128; str > 0; str >>= 1) {
        if (t < str) sh[t] += sh[t + str];
        __syncthreads();
    }
    if (t == 0) out[0] = (float)(sh[0] / (double)BATCH);
}

// ---------------------------------------------------------------------------
// Host: replicate the scan's key-split chain:
//   key = jax.random.key(42) -> data (0, 42)
//   per step: k, kh, kv = split(k, 3)
//   split: counts iota(6); pairs (i, i+3); out rows: (A0,A1),(A2,B0),(B1,B2)
// ---------------------------------------------------------------------------
extern "C" void kernel_launch(void* const* d_in, const int* in_sizes, int n_in,
                              void* d_out, int out_size) {
    const float* v_data   = (const float*)d_in[0];
    const float* kern     = (const float*)d_in[1];
    const float* b_scalar = (const float*)d_in[2];
    const float* c_vector = (const float*)d_in[3];

    RbmKeys keys;
    unsigned k0 = 0u, k1 = 42u;
    for (int t = 0; t < GIBBS_K; t++) {
        unsigned A0, B0, A1, B1, A2, B2;
        rbm_tf2x32(k0, k1, 0u, 3u, A0, B0);
        rbm_tf2x32(k0, k1, 1u, 4u, A1, B1);
        rbm_tf2x32(k0, k1, 2u, 5u, A2, B2);
        keys.kh[t] = make_uint2(A2, B0);  // keys[1]
        keys.kv[t] = make_uint2(B1, B2);  // keys[2]
        k0 = A0; k1 = A1;                 // keys[0] -> carried key
    }

    rbm_gibbs_kernel<<<NBLOCKS, TPB>>>(v_data, kern, b_scalar, c_vector, keys);
    rbm_reduce_kernel<<<1, 256>>>((float*)d_out);
}